// round 2
// baseline (speedup 1.0000x reference)
#include <cuda_runtime.h>

#define N_NODES 100000
#define E_EDGES 1200000
#define DIM 64
#define HID2 32
#define EPS_BN 1e-5f

// ---------------- scratch (static device globals; no allocation) ----------------
__device__ int   g_cnt[N_NODES];
__device__ int   g_rowptr[N_NODES + 1];
__device__ int   g_cursor[N_NODES];
__device__ int   g_csr_src[E_EDGES];
__device__ float g_Y[(size_t)N_NODES * DIM];
__device__ float g_Z[(size_t)N_NODES * DIM];
__device__ float g_H[(size_t)N_NODES * DIM];

// ---------------- CSR build ----------------
__global__ void k_zero_cnt() {
    int i = blockIdx.x * blockDim.x + threadIdx.x;
    if (i < N_NODES) g_cnt[i] = 0;
}

__global__ void k_hist(const int* __restrict__ ei) {
    int e = blockIdx.x * blockDim.x + threadIdx.x;
    if (e < E_EDGES) {
        int dst = ei[E_EDGES + e];
        if ((unsigned)dst < N_NODES) atomicAdd(&g_cnt[dst], 1);
    }
}

// single-block exclusive scan over 100K counters; also seeds cursor
__global__ void k_scan() {
    __shared__ int part[1024];
    const int CHUNK = 98;  // 1024*98 = 100352 >= N_NODES
    int t = threadIdx.x;
    int b = t * CHUNK;
    int e = b + CHUNK; if (e > N_NODES) e = N_NODES;
    int s = 0;
    for (int i = b; i < e; i++) s += g_cnt[i];
    part[t] = s;
    __syncthreads();
    for (int off = 1; off < 1024; off <<= 1) {
        int vv = (t >= off) ? part[t - off] : 0;
        __syncthreads();
        part[t] += vv;
        __syncthreads();
    }
    int run = part[t] - s;  // exclusive prefix
    for (int i = b; i < e; i++) {
        g_rowptr[i] = run;
        g_cursor[i] = run;
        run += g_cnt[i];
    }
    if (t == 1023) g_rowptr[N_NODES] = part[1023];
}

__global__ void k_fill(const int* __restrict__ ei) {
    int e = blockIdx.x * blockDim.x + threadIdx.x;
    if (e < E_EDGES) {
        int src = ei[e];
        int dst = ei[E_EDGES + e];
        if ((unsigned)dst < N_NODES && (unsigned)src < N_NODES) {
            int pos = atomicAdd(&g_cursor[dst], 1);
            g_csr_src[pos] = src;
        }
    }
}

// ---------------- O[n, j] = sum_k X[n,k] * W[j,k]   (X @ W^T), 64x64 ----------------
__global__ __launch_bounds__(256) void k_gemm64(const float* __restrict__ X,
                                                const float* __restrict__ W,
                                                float* __restrict__ O) {
    __shared__ float4 sW[64 * 16];
    int tid = threadIdx.x;
    const float4* W4 = (const float4*)W;
    for (int i = tid; i < 1024; i += 256) sW[i] = W4[i];
    __syncthreads();

    int n = blockIdx.x * 256 + tid;
    if (n >= N_NODES) return;

    float acc[64];
#pragma unroll
    for (int j = 0; j < 64; j++) acc[j] = 0.f;

    const float4* xr = (const float4*)(X + (size_t)n * DIM);
    for (int kk = 0; kk < 16; kk++) {
        float4 x4 = xr[kk];
#pragma unroll
        for (int j = 0; j < 64; j++) {
            float4 w4 = sW[j * 16 + kk];
            acc[j] = fmaf(x4.x, w4.x, acc[j]);
            acc[j] = fmaf(x4.y, w4.y, acc[j]);
            acc[j] = fmaf(x4.z, w4.z, acc[j]);
            acc[j] = fmaf(x4.w, w4.w, acc[j]);
        }
    }
    float4* o4 = (float4*)(O + (size_t)n * DIM);
#pragma unroll
    for (int j = 0; j < 16; j++)
        o4[j] = make_float4(acc[4 * j], acc[4 * j + 1], acc[4 * j + 2], acc[4 * j + 3]);
}

// ---------------- warp-per-node: H = relu(BN(sum(Y[src])/max(deg,1) + bl + Z)) ----------------
__global__ __launch_bounds__(256) void k_agg(const float* __restrict__ Y,
                                             const float* __restrict__ Z,
                                             const float* __restrict__ bl,
                                             const float* __restrict__ gam,
                                             const float* __restrict__ bet,
                                             const float* __restrict__ mu,
                                             const float* __restrict__ var,
                                             float* __restrict__ H) {
    int warp = (blockIdx.x * blockDim.x + threadIdx.x) >> 5;
    int lane = threadIdx.x & 31;
    if (warp >= N_NODES) return;

    int r0 = g_rowptr[warp];
    int r1 = g_rowptr[warp + 1];

    float a0 = 0.f, a1 = 0.f;
    for (int e = r0; e < r1; e++) {
        int s = g_csr_src[e];
        const float* yr = Y + (size_t)s * DIM;
        a0 += yr[lane];
        a1 += yr[lane + 32];
    }
    int deg = r1 - r0;
    float inv = 1.f / (float)(deg > 0 ? deg : 1);

    int j0 = lane, j1 = lane + 32;
    float h0 = a0 * inv + bl[j0] + Z[(size_t)warp * DIM + j0];
    float h1 = a1 * inv + bl[j1] + Z[(size_t)warp * DIM + j1];
    float s0 = gam[j0] * rsqrtf(var[j0] + EPS_BN);
    float s1 = gam[j1] * rsqrtf(var[j1] + EPS_BN);
    h0 = (h0 - mu[j0]) * s0 + bet[j0];
    h1 = (h1 - mu[j1]) * s1 + bet[j1];
    h0 = fmaxf(h0, 0.f);
    h1 = fmaxf(h1, 0.f);
    H[(size_t)warp * DIM + j0] = h0;
    H[(size_t)warp * DIM + j1] = h1;
}

// ---------------- MLP head: sigmoid(relu(H @ mW1^T + mb1) @ mW2^T + mb2) ----------------
__global__ __launch_bounds__(256) void k_head(const float* __restrict__ Hh,
                                              const float* __restrict__ mW1,
                                              const float* __restrict__ mb1,
                                              const float* __restrict__ mW2,
                                              const float* __restrict__ mb2,
                                              float* __restrict__ out) {
    __shared__ float4 sW[32 * 16];
    __shared__ float sb1[32];
    __shared__ float sw2[32];
    __shared__ float sb2;
    int tid = threadIdx.x;
    const float4* W4 = (const float4*)mW1;
    for (int i = tid; i < 512; i += 256) sW[i] = W4[i];
    if (tid < 32) { sb1[tid] = mb1[tid]; sw2[tid] = mW2[tid]; }
    if (tid == 0) sb2 = mb2[0];
    __syncthreads();

    int n = blockIdx.x * 256 + tid;
    if (n >= N_NODES) return;

    float acc[32];
#pragma unroll
    for (int j = 0; j < 32; j++) acc[j] = 0.f;

    const float4* xr = (const float4*)(Hh + (size_t)n * DIM);
    for (int kk = 0; kk < 16; kk++) {
        float4 x4 = xr[kk];
#pragma unroll
        for (int j = 0; j < 32; j++) {
            float4 w4 = sW[j * 16 + kk];
            acc[j] = fmaf(x4.x, w4.x, acc[j]);
            acc[j] = fmaf(x4.y, w4.y, acc[j]);
            acc[j] = fmaf(x4.z, w4.z, acc[j]);
            acc[j] = fmaf(x4.w, w4.w, acc[j]);
        }
    }
    float o = sb2;
#pragma unroll
    for (int j = 0; j < 32; j++)
        o += fmaxf(acc[j] + sb1[j], 0.f) * sw2[j];
    out[n] = 1.f / (1.f + __expf(-o));
}

// ---------------- launch ----------------
extern "C" void kernel_launch(void* const* d_in, const int* in_sizes, int n_in,
                              void* d_out, int out_size) {
    const float* x    = (const float*)d_in[0];
    const int*   ei   = (const int*)d_in[1];
    const float* Wl1  = (const float*)d_in[2];
    const float* bl1  = (const float*)d_in[3];
    const float* Wr1  = (const float*)d_in[4];
    const float* g1   = (const float*)d_in[5];
    const float* be1  = (const float*)d_in[6];
    const float* m1   = (const float*)d_in[7];
    const float* v1   = (const float*)d_in[8];
    const float* Wl2  = (const float*)d_in[9];
    const float* bl2  = (const float*)d_in[10];
    const float* Wr2  = (const float*)d_in[11];
    const float* g2   = (const float*)d_in[12];
    const float* be2  = (const float*)d_in[13];
    const float* m2   = (const float*)d_in[14];
    const float* v2   = (const float*)d_in[15];
    const float* mW1  = (const float*)d_in[16];
    const float* mb1  = (const float*)d_in[17];
    const float* mW2  = (const float*)d_in[18];
    const float* mb2  = (const float*)d_in[19];
    float* out = (float*)d_out;

    float* Y; cudaGetSymbolAddress((void**)&Y, g_Y);
    float* Z; cudaGetSymbolAddress((void**)&Z, g_Z);
    float* H; cudaGetSymbolAddress((void**)&H, g_H);

    const int NB_N = (N_NODES + 255) / 256;        // 391
    const int NB_E = (E_EDGES + 255) / 256;        // 4688
    const int NB_W = (N_NODES * 32 + 255) / 256;   // 12500

    // CSR build (once; graph shared by both layers)
    k_zero_cnt<<<NB_N, 256>>>();
    k_hist<<<NB_E, 256>>>(ei);
    k_scan<<<1, 1024>>>();
    k_fill<<<NB_E, 256>>>(ei);

    // Layer 1
    k_gemm64<<<NB_N, 256>>>(x, Wl1, Y);
    k_gemm64<<<NB_N, 256>>>(x, Wr1, Z);
    k_agg<<<NB_W, 256>>>(Y, Z, bl1, g1, be1, m1, v1, H);

    // Layer 2
    k_gemm64<<<NB_N, 256>>>(H, Wl2, Y);
    k_gemm64<<<NB_N, 256>>>(H, Wr2, Z);
    k_agg<<<NB_W, 256>>>(Y, Z, bl2, g2, be2, m2, v2, H);

    // Head
    k_head<<<NB_N, 256>>>(H, mW1, mb1, mW2, mb2, out);
}

// round 3
// speedup vs baseline: 1.5402x; 1.5402x over previous
#include <cuda_runtime.h>

#define N_NODES 100000
#define E_EDGES 1200000
#define DIM 64
#define HID2 32
#define EPS_BN 1e-5f
#define NB_SCAN 391   // ceil(N_NODES/256)

// ---------------- scratch (static device globals; no allocation) ----------------
__device__ int   g_cnt[N_NODES];
__device__ int   g_rowptr[N_NODES + 1];
__device__ int   g_cursor[N_NODES];
__device__ int   g_csr_src[E_EDGES];
__device__ int   g_part[NB_SCAN];
__device__ float g_Y[(size_t)N_NODES * DIM];
__device__ float g_Z[(size_t)N_NODES * DIM];
__device__ float g_H[(size_t)N_NODES * DIM];

// ---------------- CSR build ----------------
__global__ void k_zero_cnt() {
    int i = blockIdx.x * blockDim.x + threadIdx.x;
    if (i < N_NODES) g_cnt[i] = 0;
}

__global__ void k_hist(const int* __restrict__ ei) {
    int e = blockIdx.x * blockDim.x + threadIdx.x;
    if (e < E_EDGES) {
        int dst = ei[E_EDGES + e];
        if ((unsigned)dst < N_NODES) atomicAdd(&g_cnt[dst], 1);
    }
}

// pass A: per-block sums of 256 counters
__global__ __launch_bounds__(256) void k_blocksum() {
    __shared__ int sc[256];
    int t = threadIdx.x;
    int i = blockIdx.x * 256 + t;
    int v = (i < N_NODES) ? g_cnt[i] : 0;
    sc[t] = v;
    __syncthreads();
    for (int off = 128; off > 0; off >>= 1) {
        if (t < off) sc[t] += sc[t + off];
        __syncthreads();
    }
    if (t == 0) g_part[blockIdx.x] = sc[0];
}

// pass B: 1-block exclusive scan over 391 partials
__global__ __launch_bounds__(512) void k_scanpart() {
    __shared__ int sp[512];
    int t = threadIdx.x;
    int v = (t < NB_SCAN) ? g_part[t] : 0;
    sp[t] = v;
    __syncthreads();
    for (int off = 1; off < 512; off <<= 1) {
        int u = (t >= off) ? sp[t - off] : 0;
        __syncthreads();
        sp[t] += u;
        __syncthreads();
    }
    if (t < NB_SCAN) g_part[t] = sp[t] - v;   // exclusive
    if (t == 0) g_rowptr[N_NODES] = sp[511];  // total (zeros beyond NB_SCAN)
}

// pass C: local scan + global offset -> rowptr, cursor
__global__ __launch_bounds__(256) void k_scatter() {
    __shared__ int sc[256];
    int t = threadIdx.x;
    int i = blockIdx.x * 256 + t;
    int v = (i < N_NODES) ? g_cnt[i] : 0;
    sc[t] = v;
    __syncthreads();
    for (int off = 1; off < 256; off <<= 1) {
        int u = (t >= off) ? sc[t - off] : 0;
        __syncthreads();
        sc[t] += u;
        __syncthreads();
    }
    if (i < N_NODES) {
        int pos = g_part[blockIdx.x] + sc[t] - v;
        g_rowptr[i] = pos;
        g_cursor[i] = pos;
    }
}

__global__ void k_fill(const int* __restrict__ ei) {
    int e = blockIdx.x * blockDim.x + threadIdx.x;
    if (e < E_EDGES) {
        int src = ei[e];
        int dst = ei[E_EDGES + e];
        if ((unsigned)dst < N_NODES && (unsigned)src < N_NODES) {
            int pos = atomicAdd(&g_cursor[dst], 1);
            g_csr_src[pos] = src;
        }
    }
}

// ---------------- O[n, j] = sum_k X[n,k] * W[j,k]   (X @ W^T), 64x64 ----------------
__global__ __launch_bounds__(256) void k_gemm64(const float* __restrict__ X,
                                                const float* __restrict__ W,
                                                float* __restrict__ O) {
    __shared__ float4 sW[64 * 16];
    int tid = threadIdx.x;
    const float4* W4 = (const float4*)W;
    for (int i = tid; i < 1024; i += 256) sW[i] = W4[i];
    __syncthreads();

    int n = blockIdx.x * 256 + tid;
    if (n >= N_NODES) return;

    float acc[64];
#pragma unroll
    for (int j = 0; j < 64; j++) acc[j] = 0.f;

    const float4* xr = (const float4*)(X + (size_t)n * DIM);
#pragma unroll
    for (int kk = 0; kk < 16; kk++) {
        float4 x4 = xr[kk];
#pragma unroll
        for (int j = 0; j < 64; j++) {
            float4 w4 = sW[j * 16 + kk];
            acc[j] = fmaf(x4.x, w4.x, acc[j]);
            acc[j] = fmaf(x4.y, w4.y, acc[j]);
            acc[j] = fmaf(x4.z, w4.z, acc[j]);
            acc[j] = fmaf(x4.w, w4.w, acc[j]);
        }
    }
    float4* o4 = (float4*)(O + (size_t)n * DIM);
#pragma unroll
    for (int j = 0; j < 16; j++)
        o4[j] = make_float4(acc[4 * j], acc[4 * j + 1], acc[4 * j + 2], acc[4 * j + 3]);
}

// ---------------- warp-per-node: H = relu(BN(sum(Y[src])/max(deg,1) + bl + Z)) ----------------
// lane handles features (2*lane, 2*lane+1) via float2 -> one LDG.64 warp-instr per edge
__global__ __launch_bounds__(256) void k_agg(const float* __restrict__ Y,
                                             const float* __restrict__ Z,
                                             const float* __restrict__ bl,
                                             const float* __restrict__ gam,
                                             const float* __restrict__ bet,
                                             const float* __restrict__ mu,
                                             const float* __restrict__ var,
                                             float* __restrict__ H) {
    int warp = (blockIdx.x * blockDim.x + threadIdx.x) >> 5;
    int lane = threadIdx.x & 31;
    if (warp >= N_NODES) return;

    int r0 = g_rowptr[warp];
    int r1 = g_rowptr[warp + 1];

    const float2* Y2 = (const float2*)Y;
    float ax = 0.f, ay = 0.f;

    int e = r0;
    for (; e + 4 <= r1; e += 4) {
        int s0 = g_csr_src[e];
        int s1 = g_csr_src[e + 1];
        int s2 = g_csr_src[e + 2];
        int s3 = g_csr_src[e + 3];
        float2 v0 = Y2[(size_t)s0 * 32 + lane];
        float2 v1 = Y2[(size_t)s1 * 32 + lane];
        float2 v2 = Y2[(size_t)s2 * 32 + lane];
        float2 v3 = Y2[(size_t)s3 * 32 + lane];
        ax += (v0.x + v1.x) + (v2.x + v3.x);
        ay += (v0.y + v1.y) + (v2.y + v3.y);
    }
    if (e + 2 <= r1) {
        int s0 = g_csr_src[e];
        int s1 = g_csr_src[e + 1];
        float2 v0 = Y2[(size_t)s0 * 32 + lane];
        float2 v1 = Y2[(size_t)s1 * 32 + lane];
        ax += v0.x + v1.x;
        ay += v0.y + v1.y;
        e += 2;
    }
    if (e < r1) {
        float2 v = Y2[(size_t)g_csr_src[e] * 32 + lane];
        ax += v.x;
        ay += v.y;
    }

    int deg = r1 - r0;
    float inv = 1.f / (float)(deg > 0 ? deg : 1);

    int j0 = 2 * lane, j1 = 2 * lane + 1;
    float2 z = ((const float2*)Z)[(size_t)warp * 32 + lane];
    float h0 = ax * inv + bl[j0] + z.x;
    float h1 = ay * inv + bl[j1] + z.y;
    float s0 = gam[j0] * rsqrtf(var[j0] + EPS_BN);
    float s1 = gam[j1] * rsqrtf(var[j1] + EPS_BN);
    h0 = fmaxf((h0 - mu[j0]) * s0 + bet[j0], 0.f);
    h1 = fmaxf((h1 - mu[j1]) * s1 + bet[j1], 0.f);
    ((float2*)H)[(size_t)warp * 32 + lane] = make_float2(h0, h1);
}

// ---------------- MLP head: sigmoid(relu(H @ mW1^T + mb1) @ mW2^T + mb2) ----------------
__global__ __launch_bounds__(256) void k_head(const float* __restrict__ Hh,
                                              const float* __restrict__ mW1,
                                              const float* __restrict__ mb1,
                                              const float* __restrict__ mW2,
                                              const float* __restrict__ mb2,
                                              float* __restrict__ out) {
    __shared__ float4 sW[32 * 16];
    __shared__ float sb1[32];
    __shared__ float sw2[32];
    __shared__ float sb2;
    int tid = threadIdx.x;
    const float4* W4 = (const float4*)mW1;
    for (int i = tid; i < 512; i += 256) sW[i] = W4[i];
    if (tid < 32) { sb1[tid] = mb1[tid]; sw2[tid] = mW2[tid]; }
    if (tid == 0) sb2 = mb2[0];
    __syncthreads();

    int n = blockIdx.x * 256 + tid;
    if (n >= N_NODES) return;

    float acc[32];
#pragma unroll
    for (int j = 0; j < 32; j++) acc[j] = 0.f;

    const float4* xr = (const float4*)(Hh + (size_t)n * DIM);
#pragma unroll
    for (int kk = 0; kk < 16; kk++) {
        float4 x4 = xr[kk];
#pragma unroll
        for (int j = 0; j < 32; j++) {
            float4 w4 = sW[j * 16 + kk];
            acc[j] = fmaf(x4.x, w4.x, acc[j]);
            acc[j] = fmaf(x4.y, w4.y, acc[j]);
            acc[j] = fmaf(x4.z, w4.z, acc[j]);
            acc[j] = fmaf(x4.w, w4.w, acc[j]);
        }
    }
    float o = sb2;
#pragma unroll
    for (int j = 0; j < 32; j++)
        o += fmaxf(acc[j] + sb1[j], 0.f) * sw2[j];
    out[n] = 1.f / (1.f + __expf(-o));
}

// ---------------- launch ----------------
extern "C" void kernel_launch(void* const* d_in, const int* in_sizes, int n_in,
                              void* d_out, int out_size) {
    const float* x    = (const float*)d_in[0];
    const int*   ei   = (const int*)d_in[1];
    const float* Wl1  = (const float*)d_in[2];
    const float* bl1  = (const float*)d_in[3];
    const float* Wr1  = (const float*)d_in[4];
    const float* g1   = (const float*)d_in[5];
    const float* be1  = (const float*)d_in[6];
    const float* m1   = (const float*)d_in[7];
    const float* v1   = (const float*)d_in[8];
    const float* Wl2  = (const float*)d_in[9];
    const float* bl2  = (const float*)d_in[10];
    const float* Wr2  = (const float*)d_in[11];
    const float* g2   = (const float*)d_in[12];
    const float* be2  = (const float*)d_in[13];
    const float* m2   = (const float*)d_in[14];
    const float* v2   = (const float*)d_in[15];
    const float* mW1  = (const float*)d_in[16];
    const float* mb1  = (const float*)d_in[17];
    const float* mW2  = (const float*)d_in[18];
    const float* mb2  = (const float*)d_in[19];
    float* out = (float*)d_out;

    float* Y; cudaGetSymbolAddress((void**)&Y, g_Y);
    float* Z; cudaGetSymbolAddress((void**)&Z, g_Z);
    float* H; cudaGetSymbolAddress((void**)&H, g_H);

    const int NB_N = (N_NODES + 255) / 256;        // 391
    const int NB_E = (E_EDGES + 255) / 256;        // 4688
    const int NB_W = (N_NODES * 32 + 255) / 256;   // 12500

    // CSR build (once; graph shared by both layers)
    k_zero_cnt<<<NB_N, 256>>>();
    k_hist<<<NB_E, 256>>>(ei);
    k_blocksum<<<NB_SCAN, 256>>>();
    k_scanpart<<<1, 512>>>();
    k_scatter<<<NB_SCAN, 256>>>();
    k_fill<<<NB_E, 256>>>(ei);

    // Layer 1
    k_gemm64<<<NB_N, 256>>>(x, Wl1, Y);
    k_gemm64<<<NB_N, 256>>>(x, Wr1, Z);
    k_agg<<<NB_W, 256>>>(Y, Z, bl1, g1, be1, m1, v1, H);

    // Layer 2
    k_gemm64<<<NB_N, 256>>>(H, Wl2, Y);
    k_gemm64<<<NB_N, 256>>>(H, Wr2, Z);
    k_agg<<<NB_W, 256>>>(Y, Z, bl2, g2, be2, m2, v2, H);

    // Head
    k_head<<<NB_N, 256>>>(H, mW1, mb1, mW2, mb2, out);
}

// round 4
// speedup vs baseline: 1.6403x; 1.0650x over previous
#include <cuda_runtime.h>

#define N_NODES 100000
#define E_EDGES 1200000
#define DIM 64
#define HID2 32
#define EPS_BN 1e-5f
#define NB_N 391      // ceil(N_NODES/256)
#define NB_E 4688     // ceil(E_EDGES/256)

// ---------------- scratch (static device globals; no allocation) ----------------
__device__ int   g_cnt[N_NODES];
__device__ int   g_rowptr[N_NODES + 1];
__device__ int   g_cursor[N_NODES];
__device__ int   g_csr_src[E_EDGES];
__device__ int   g_part[NB_N];
__device__ float g_Y[(size_t)N_NODES * DIM];
__device__ float g_Z[(size_t)N_NODES * DIM];
__device__ float g_H[(size_t)N_NODES * DIM];

// ---------------- f32x2 packed math helpers ----------------
__device__ __forceinline__ unsigned long long ffma2(unsigned long long a,
                                                    unsigned long long b,
                                                    unsigned long long c) {
    unsigned long long d;
    asm("fma.rn.f32x2 %0, %1, %2, %3;" : "=l"(d) : "l"(a), "l"(b), "l"(c));
    return d;
}
__device__ __forceinline__ unsigned long long dup2(float x) {
    unsigned long long d;
    unsigned u = __float_as_uint(x);
    asm("mov.b64 %0, {%1, %1};" : "=l"(d) : "r"(u));
    return d;
}
__device__ __forceinline__ float lo32(unsigned long long v) {
    return __uint_as_float((unsigned)(v & 0xffffffffull));
}
__device__ __forceinline__ float hi32(unsigned long long v) {
    return __uint_as_float((unsigned)(v >> 32));
}

// ---------------- GEMM body: O[n,j] = sum_k X[n,k]*W[j,k], 64x64, f32x2 ----------------
// sWp layout: sWp[k*32+p] = (W[2p][k], W[2p+1][k])
__device__ __forceinline__ void gemm64_body(const float* __restrict__ X,
                                            const float* __restrict__ W,
                                            float* __restrict__ O,
                                            int blk, float2* sWp) {
    int tid = threadIdx.x;
    for (int i = tid; i < 2048; i += 256) {
        int p = i >> 6, k = i & 63;
        sWp[k * 32 + p] = make_float2(W[(2 * p) * 64 + k], W[(2 * p + 1) * 64 + k]);
    }
    __syncthreads();

    int n = blk * 256 + tid;
    if (n >= N_NODES) return;

    unsigned long long acc[32];
#pragma unroll
    for (int p = 0; p < 32; p++) acc[p] = 0ull;

    const float4* xr = (const float4*)(X + (size_t)n * DIM);
#pragma unroll 2
    for (int kk = 0; kk < 16; kk++) {
        float4 x4 = xr[kk];
        float xs[4] = {x4.x, x4.y, x4.z, x4.w};
#pragma unroll
        for (int t = 0; t < 4; t++) {
            int k = kk * 4 + t;
            unsigned long long x2 = dup2(xs[t]);
            const ulonglong2* wrow = (const ulonglong2*)(sWp + k * 32);
#pragma unroll
            for (int q = 0; q < 16; q++) {
                ulonglong2 w2 = wrow[q];
                acc[2 * q]     = ffma2(x2, w2.x, acc[2 * q]);
                acc[2 * q + 1] = ffma2(x2, w2.y, acc[2 * q + 1]);
            }
        }
    }
    ulonglong2* o2 = (ulonglong2*)(O + (size_t)n * DIM);
#pragma unroll
    for (int q = 0; q < 16; q++) o2[q] = make_ulonglong2(acc[2 * q], acc[2 * q + 1]);
}

// ---------------- fused: [gemm Y1 | gemm Z1 | hist] ----------------
__global__ __launch_bounds__(256, 2) void k_fusedA(const float* __restrict__ x,
                                                   const float* __restrict__ Wl,
                                                   const float* __restrict__ Wr,
                                                   const int* __restrict__ ei,
                                                   float* __restrict__ Y,
                                                   float* __restrict__ Z) {
    __shared__ float2 sWp[2048];
    int b = blockIdx.x;
    if (b < NB_N) {
        gemm64_body(x, Wl, Y, b, sWp);
    } else if (b < 2 * NB_N) {
        gemm64_body(x, Wr, Z, b - NB_N, sWp);
    } else {
        int e = (b - 2 * NB_N) * 256 + threadIdx.x;
        if (e < E_EDGES) {
            int dst = ei[E_EDGES + e];
            if ((unsigned)dst < N_NODES) atomicAdd(&g_cnt[dst], 1);
        }
    }
}

// ---------------- fused: [gemm Y2 | gemm Z2] ----------------
__global__ __launch_bounds__(256, 2) void k_fusedB(const float* __restrict__ Hh,
                                                   const float* __restrict__ Wl,
                                                   const float* __restrict__ Wr,
                                                   float* __restrict__ Y,
                                                   float* __restrict__ Z) {
    __shared__ float2 sWp[2048];
    int b = blockIdx.x;
    if (b < NB_N) gemm64_body(Hh, Wl, Y, b, sWp);
    else          gemm64_body(Hh, Wr, Z, b - NB_N, sWp);
}

// ---------------- CSR build ----------------
__global__ void k_zero_cnt() {
    int i = blockIdx.x * blockDim.x + threadIdx.x;
    if (i < N_NODES) g_cnt[i] = 0;
}

// pass A: per-block sums of 256 counters
__global__ __launch_bounds__(256) void k_blocksum() {
    __shared__ int sc[256];
    int t = threadIdx.x;
    int i = blockIdx.x * 256 + t;
    int v = (i < N_NODES) ? g_cnt[i] : 0;
    sc[t] = v;
    __syncthreads();
    for (int off = 128; off > 0; off >>= 1) {
        if (t < off) sc[t] += sc[t + off];
        __syncthreads();
    }
    if (t == 0) g_part[blockIdx.x] = sc[0];
}

// pass B: 1-block exclusive scan over NB_N partials
__global__ __launch_bounds__(512) void k_scanpart() {
    __shared__ int sp[512];
    int t = threadIdx.x;
    int v = (t < NB_N) ? g_part[t] : 0;
    sp[t] = v;
    __syncthreads();
    for (int off = 1; off < 512; off <<= 1) {
        int u = (t >= off) ? sp[t - off] : 0;
        __syncthreads();
        sp[t] += u;
        __syncthreads();
    }
    if (t < NB_N) g_part[t] = sp[t] - v;      // exclusive
    if (t == 0) g_rowptr[N_NODES] = sp[511];  // total
}

// pass C: local scan + global offset -> rowptr, cursor
__global__ __launch_bounds__(256) void k_scatter() {
    __shared__ int sc[256];
    int t = threadIdx.x;
    int i = blockIdx.x * 256 + t;
    int v = (i < N_NODES) ? g_cnt[i] : 0;
    sc[t] = v;
    __syncthreads();
    for (int off = 1; off < 256; off <<= 1) {
        int u = (t >= off) ? sc[t - off] : 0;
        __syncthreads();
        sc[t] += u;
        __syncthreads();
    }
    if (i < N_NODES) {
        int pos = g_part[blockIdx.x] + sc[t] - v;
        g_rowptr[i] = pos;
        g_cursor[i] = pos;
    }
}

__global__ void k_fill(const int* __restrict__ ei) {
    int e = blockIdx.x * blockDim.x + threadIdx.x;
    if (e < E_EDGES) {
        int src = ei[e];
        int dst = ei[E_EDGES + e];
        if ((unsigned)dst < N_NODES && (unsigned)src < N_NODES) {
            int pos = atomicAdd(&g_cursor[dst], 1);
            g_csr_src[pos] = src;
        }
    }
}

// ---------------- warp-per-node: H = relu(BN(sum(Y[src])/max(deg,1) + bl + Z)) ----------------
__global__ __launch_bounds__(256) void k_agg(const float* __restrict__ Y,
                                             const float* __restrict__ Z,
                                             const float* __restrict__ bl,
                                             const float* __restrict__ gam,
                                             const float* __restrict__ bet,
                                             const float* __restrict__ mu,
                                             const float* __restrict__ var,
                                             float* __restrict__ H) {
    int warp = (blockIdx.x * blockDim.x + threadIdx.x) >> 5;
    int lane = threadIdx.x & 31;
    if (warp >= N_NODES) return;

    int r0 = g_rowptr[warp];
    int r1 = g_rowptr[warp + 1];

    const float2* Y2 = (const float2*)Y;
    float ax = 0.f, ay = 0.f;

    int e = r0;
    for (; e + 4 <= r1; e += 4) {
        int s0 = g_csr_src[e];
        int s1 = g_csr_src[e + 1];
        int s2 = g_csr_src[e + 2];
        int s3 = g_csr_src[e + 3];
        float2 v0 = Y2[(size_t)s0 * 32 + lane];
        float2 v1 = Y2[(size_t)s1 * 32 + lane];
        float2 v2 = Y2[(size_t)s2 * 32 + lane];
        float2 v3 = Y2[(size_t)s3 * 32 + lane];
        ax += (v0.x + v1.x) + (v2.x + v3.x);
        ay += (v0.y + v1.y) + (v2.y + v3.y);
    }
    if (e + 2 <= r1) {
        int s0 = g_csr_src[e];
        int s1 = g_csr_src[e + 1];
        float2 v0 = Y2[(size_t)s0 * 32 + lane];
        float2 v1 = Y2[(size_t)s1 * 32 + lane];
        ax += v0.x + v1.x;
        ay += v0.y + v1.y;
        e += 2;
    }
    if (e < r1) {
        float2 v = Y2[(size_t)g_csr_src[e] * 32 + lane];
        ax += v.x;
        ay += v.y;
    }

    int deg = r1 - r0;
    float inv = 1.f / (float)(deg > 0 ? deg : 1);

    int j0 = 2 * lane, j1 = 2 * lane + 1;
    float2 z = ((const float2*)Z)[(size_t)warp * 32 + lane];
    float h0 = ax * inv + bl[j0] + z.x;
    float h1 = ay * inv + bl[j1] + z.y;
    float s0 = gam[j0] * rsqrtf(var[j0] + EPS_BN);
    float s1 = gam[j1] * rsqrtf(var[j1] + EPS_BN);
    h0 = fmaxf((h0 - mu[j0]) * s0 + bet[j0], 0.f);
    h1 = fmaxf((h1 - mu[j1]) * s1 + bet[j1], 0.f);
    ((float2*)H)[(size_t)warp * 32 + lane] = make_float2(h0, h1);
}

// ---------------- MLP head: sigmoid(relu(H @ mW1^T + mb1) @ mW2^T + mb2) ----------------
__global__ __launch_bounds__(256) void k_head(const float* __restrict__ Hh,
                                              const float* __restrict__ mW1,
                                              const float* __restrict__ mb1,
                                              const float* __restrict__ mW2,
                                              const float* __restrict__ mb2,
                                              float* __restrict__ out) {
    __shared__ float2 sWp[64 * 16];  // sWp[k*16+p] = (mW1[2p][k], mW1[2p+1][k])
    __shared__ float sb1[32];
    __shared__ float sw2[32];
    __shared__ float sb2;
    int tid = threadIdx.x;
    for (int i = tid; i < 1024; i += 256) {
        int p = i >> 6, k = i & 63;
        sWp[k * 16 + p] = make_float2(mW1[(2 * p) * 64 + k], mW1[(2 * p + 1) * 64 + k]);
    }
    if (tid < 32) { sb1[tid] = mb1[tid]; sw2[tid] = mW2[tid]; }
    if (tid == 0) sb2 = mb2[0];
    __syncthreads();

    int n = blockIdx.x * 256 + tid;
    if (n >= N_NODES) return;

    unsigned long long acc[16];
#pragma unroll
    for (int p = 0; p < 16; p++) acc[p] = 0ull;

    const float4* xr = (const float4*)(Hh + (size_t)n * DIM);
#pragma unroll 4
    for (int kk = 0; kk < 16; kk++) {
        float4 x4 = xr[kk];
        float xs[4] = {x4.x, x4.y, x4.z, x4.w};
#pragma unroll
        for (int t = 0; t < 4; t++) {
            int k = kk * 4 + t;
            unsigned long long x2 = dup2(xs[t]);
            const ulonglong2* wrow = (const ulonglong2*)(sWp + k * 16);
#pragma unroll
            for (int q = 0; q < 8; q++) {
                ulonglong2 w2 = wrow[q];
                acc[2 * q]     = ffma2(x2, w2.x, acc[2 * q]);
                acc[2 * q + 1] = ffma2(x2, w2.y, acc[2 * q + 1]);
            }
        }
    }
    float o = sb2;
#pragma unroll
    for (int p = 0; p < 16; p++) {
        o += fmaxf(lo32(acc[p]) + sb1[2 * p], 0.f) * sw2[2 * p];
        o += fmaxf(hi32(acc[p]) + sb1[2 * p + 1], 0.f) * sw2[2 * p + 1];
    }
    out[n] = 1.f / (1.f + __expf(-o));
}

// ---------------- launch ----------------
extern "C" void kernel_launch(void* const* d_in, const int* in_sizes, int n_in,
                              void* d_out, int out_size) {
    const float* x    = (const float*)d_in[0];
    const int*   ei   = (const int*)d_in[1];
    const float* Wl1  = (const float*)d_in[2];
    const float* bl1  = (const float*)d_in[3];
    const float* Wr1  = (const float*)d_in[4];
    const float* g1   = (const float*)d_in[5];
    const float* be1  = (const float*)d_in[6];
    const float* m1   = (const float*)d_in[7];
    const float* v1   = (const float*)d_in[8];
    const float* Wl2  = (const float*)d_in[9];
    const float* bl2  = (const float*)d_in[10];
    const float* Wr2  = (const float*)d_in[11];
    const float* g2   = (const float*)d_in[12];
    const float* be2  = (const float*)d_in[13];
    const float* m2   = (const float*)d_in[14];
    const float* v2   = (const float*)d_in[15];
    const float* mW1  = (const float*)d_in[16];
    const float* mb1  = (const float*)d_in[17];
    const float* mW2  = (const float*)d_in[18];
    const float* mb2  = (const float*)d_in[19];
    float* out = (float*)d_out;

    float* Y; cudaGetSymbolAddress((void**)&Y, g_Y);
    float* Z; cudaGetSymbolAddress((void**)&Z, g_Z);
    float* H; cudaGetSymbolAddress((void**)&H, g_H);

    const int NB_W = (N_NODES * 32 + 255) / 256;   // 12500

    k_zero_cnt<<<NB_N, 256>>>();

    // overlapped: layer-1 GEMM pair + degree histogram
    k_fusedA<<<2 * NB_N + NB_E, 256>>>(x, Wl1, Wr1, ei, Y, Z);

    // CSR finalize
    k_blocksum<<<NB_N, 256>>>();
    k_scanpart<<<1, 512>>>();
    k_scatter<<<NB_N, 256>>>();
    k_fill<<<NB_E, 256>>>(ei);

    // Layer 1 aggregate
    k_agg<<<NB_W, 256>>>(Y, Z, bl1, g1, be1, m1, v1, H);

    // Layer 2
    k_fusedB<<<2 * NB_N, 256>>>(H, Wl2, Wr2, Y, Z);
    k_agg<<<NB_W, 256>>>(Y, Z, bl2, g2, be2, m2, v2, H);

    // Head
    k_head<<<NB_N, 256>>>(H, mW1, mb1, mW2, mb2, out);
}

// round 5
// speedup vs baseline: 1.6840x; 1.0267x over previous
#include <cuda_runtime.h>

#define N_NODES 100000
#define E_EDGES 1200000
#define DIM 64
#define HID2 32
#define EPS_BN 1e-5f
#define NB_N 391      // ceil(N_NODES/256)
#define NB_E 4688     // ceil(E_EDGES/256)

// ---------------- scratch (static device globals; no allocation) ----------------
__device__ int   g_cnt[N_NODES];
__device__ int   g_rowptr[N_NODES + 1];
__device__ int   g_cursor[N_NODES];
__device__ int   g_csr_src[E_EDGES];
__device__ int   g_part[NB_N];
__device__ float g_Y[(size_t)N_NODES * DIM];
__device__ float g_Z[(size_t)N_NODES * DIM];
__device__ float g_H[(size_t)N_NODES * DIM];

// ---------------- f32x2 packed math helpers ----------------
__device__ __forceinline__ unsigned long long ffma2(unsigned long long a,
                                                    unsigned long long b,
                                                    unsigned long long c) {
    unsigned long long d;
    asm("fma.rn.f32x2 %0, %1, %2, %3;" : "=l"(d) : "l"(a), "l"(b), "l"(c));
    return d;
}
__device__ __forceinline__ unsigned long long dup2(float x) {
    unsigned long long d;
    unsigned u = __float_as_uint(x);
    asm("mov.b64 %0, {%1, %1};" : "=l"(d) : "r"(u));
    return d;
}
__device__ __forceinline__ float lo32(unsigned long long v) {
    return __uint_as_float((unsigned)(v & 0xffffffffull));
}
__device__ __forceinline__ float hi32(unsigned long long v) {
    return __uint_as_float((unsigned)(v >> 32));
}

// ---------------- GEMM body: O[n,j] = sum_k X[n,k]*W[j,k], 64x64 ----------------
__device__ __forceinline__ void gemm64_body(const float* __restrict__ X,
                                            const float* __restrict__ W,
                                            float* __restrict__ O,
                                            int blk, float2* sWp) {
    int tid = threadIdx.x;
    for (int i = tid; i < 2048; i += 256) {
        int p = i >> 6, k = i & 63;
        sWp[k * 32 + p] = make_float2(W[(2 * p) * 64 + k], W[(2 * p + 1) * 64 + k]);
    }
    __syncthreads();

    int n = blk * 256 + tid;
    if (n >= N_NODES) return;

    unsigned long long acc[32];
#pragma unroll
    for (int p = 0; p < 32; p++) acc[p] = 0ull;

    const float4* xr = (const float4*)(X + (size_t)n * DIM);
#pragma unroll 2
    for (int kk = 0; kk < 16; kk++) {
        float4 x4 = xr[kk];
        float xs[4] = {x4.x, x4.y, x4.z, x4.w};
#pragma unroll
        for (int t = 0; t < 4; t++) {
            int k = kk * 4 + t;
            unsigned long long x2 = dup2(xs[t]);
            const ulonglong2* wrow = (const ulonglong2*)(sWp + k * 32);
#pragma unroll
            for (int q = 0; q < 16; q++) {
                ulonglong2 w2 = wrow[q];
                acc[2 * q]     = ffma2(x2, w2.x, acc[2 * q]);
                acc[2 * q + 1] = ffma2(x2, w2.y, acc[2 * q + 1]);
            }
        }
    }
    ulonglong2* o2 = (ulonglong2*)(O + (size_t)n * DIM);
#pragma unroll
    for (int q = 0; q < 16; q++) o2[q] = make_ulonglong2(acc[2 * q], acc[2 * q + 1]);
}

// ---------------- gemm pair: [X@Wl^T -> Y | X@Wr^T -> Z] ----------------
__global__ __launch_bounds__(256, 2) void k_gemmpair(const float* __restrict__ X,
                                                     const float* __restrict__ Wl,
                                                     const float* __restrict__ Wr,
                                                     float* __restrict__ Y,
                                                     float* __restrict__ Z) {
    __shared__ float2 sWp[2048];
    int b = blockIdx.x;
    if (b < NB_N) gemm64_body(X, Wl, Y, b, sWp);
    else          gemm64_body(X, Wr, Z, b - NB_N, sWp);
}

// ---------------- CSR build ----------------
__global__ void k_zero_cnt() {
    int i = blockIdx.x * blockDim.x + threadIdx.x;
    if (i < N_NODES) g_cnt[i] = 0;
}

__global__ void k_hist(const int* __restrict__ ei) {
    int e = blockIdx.x * blockDim.x + threadIdx.x;
    if (e < E_EDGES) {
        int dst = ei[E_EDGES + e];
        if ((unsigned)dst < N_NODES) atomicAdd(&g_cnt[dst], 1);
    }
}

// per-block sums of 256 counters
__global__ __launch_bounds__(256) void k_blocksum() {
    __shared__ int sc[256];
    int t = threadIdx.x;
    int i = blockIdx.x * 256 + t;
    int v = (i < N_NODES) ? g_cnt[i] : 0;
    sc[t] = v;
    __syncthreads();
    for (int off = 128; off > 0; off >>= 1) {
        if (t < off) sc[t] += sc[t + off];
        __syncthreads();
    }
    if (t == 0) g_part[blockIdx.x] = sc[0];
}

// scatter with inline lookback over raw block partials: rowptr, cursor
__global__ __launch_bounds__(256) void k_scatter2() {
    __shared__ int sc[256];
    __shared__ int sbase[8];
    int t = threadIdx.x;
    int b = blockIdx.x;

    // base = sum of g_part[0..b)
    int acc = 0;
    for (int i = t; i < b; i += 256) acc += g_part[i];
#pragma unroll
    for (int o = 16; o > 0; o >>= 1) acc += __shfl_down_sync(0xffffffffu, acc, o);
    if ((t & 31) == 0) sbase[t >> 5] = acc;

    int i = b * 256 + t;
    int v = (i < N_NODES) ? g_cnt[i] : 0;
    sc[t] = v;
    __syncthreads();

    int base = 0;
#pragma unroll
    for (int w = 0; w < 8; w++) base += sbase[w];

    for (int off = 1; off < 256; off <<= 1) {
        int u = (t >= off) ? sc[t - off] : 0;
        __syncthreads();
        sc[t] += u;
        __syncthreads();
    }
    if (i < N_NODES) {
        int pos = base + sc[t] - v;
        g_rowptr[i] = pos;
        g_cursor[i] = pos;
    }
    if (b == NB_N - 1 && t == 255) g_rowptr[N_NODES] = base + sc[255];
}

__global__ void k_fill(const int* __restrict__ ei) {
    int e = blockIdx.x * blockDim.x + threadIdx.x;
    if (e < E_EDGES) {
        int src = ei[e];
        int dst = ei[E_EDGES + e];
        if ((unsigned)dst < N_NODES && (unsigned)src < N_NODES) {
            int pos = atomicAdd(&g_cursor[dst], 1);
            g_csr_src[pos] = src;
        }
    }
}

// ---------------- warp-per-node: H = relu(BN(sum(Y[src])/max(deg,1) + bl + Z)) ----------------
__global__ __launch_bounds__(256) void k_agg(const float* __restrict__ Y,
                                             const float* __restrict__ Z,
                                             const float* __restrict__ bl,
                                             const float* __restrict__ gam,
                                             const float* __restrict__ bet,
                                             const float* __restrict__ mu,
                                             const float* __restrict__ var,
                                             float* __restrict__ H) {
    int warp = (blockIdx.x * blockDim.x + threadIdx.x) >> 5;
    int lane = threadIdx.x & 31;
    if (warp >= N_NODES) return;

    int r0 = g_rowptr[warp];
    int r1 = g_rowptr[warp + 1];

    const float2* Y2 = (const float2*)Y;
    float ax = 0.f, ay = 0.f;

    int e = r0;
    for (; e + 4 <= r1; e += 4) {
        int s0 = g_csr_src[e];
        int s1 = g_csr_src[e + 1];
        int s2 = g_csr_src[e + 2];
        int s3 = g_csr_src[e + 3];
        float2 v0 = Y2[(size_t)s0 * 32 + lane];
        float2 v1 = Y2[(size_t)s1 * 32 + lane];
        float2 v2 = Y2[(size_t)s2 * 32 + lane];
        float2 v3 = Y2[(size_t)s3 * 32 + lane];
        ax += (v0.x + v1.x) + (v2.x + v3.x);
        ay += (v0.y + v1.y) + (v2.y + v3.y);
    }
    if (e + 2 <= r1) {
        int s0 = g_csr_src[e];
        int s1 = g_csr_src[e + 1];
        float2 v0 = Y2[(size_t)s0 * 32 + lane];
        float2 v1 = Y2[(size_t)s1 * 32 + lane];
        ax += v0.x + v1.x;
        ay += v0.y + v1.y;
        e += 2;
    }
    if (e < r1) {
        float2 v = Y2[(size_t)g_csr_src[e] * 32 + lane];
        ax += v.x;
        ay += v.y;
    }

    int deg = r1 - r0;
    float inv = 1.f / (float)(deg > 0 ? deg : 1);

    int j0 = 2 * lane, j1 = 2 * lane + 1;
    float2 z = ((const float2*)Z)[(size_t)warp * 32 + lane];
    float h0 = ax * inv + bl[j0] + z.x;
    float h1 = ay * inv + bl[j1] + z.y;
    float s0 = gam[j0] * rsqrtf(var[j0] + EPS_BN);
    float s1 = gam[j1] * rsqrtf(var[j1] + EPS_BN);
    h0 = fmaxf((h0 - mu[j0]) * s0 + bet[j0], 0.f);
    h1 = fmaxf((h1 - mu[j1]) * s1 + bet[j1], 0.f);
    ((float2*)H)[(size_t)warp * 32 + lane] = make_float2(h0, h1);
}

// ---------------- MLP head: sigmoid(relu(H @ mW1^T + mb1) @ mW2^T + mb2) ----------------
__global__ __launch_bounds__(256) void k_head(const float* __restrict__ Hh,
                                              const float* __restrict__ mW1,
                                              const float* __restrict__ mb1,
                                              const float* __restrict__ mW2,
                                              const float* __restrict__ mb2,
                                              float* __restrict__ out) {
    __shared__ float2 sWp[64 * 16];
    __shared__ float sb1[32];
    __shared__ float sw2[32];
    __shared__ float sb2;
    int tid = threadIdx.x;
    for (int i = tid; i < 1024; i += 256) {
        int p = i >> 6, k = i & 63;
        sWp[k * 16 + p] = make_float2(mW1[(2 * p) * 64 + k], mW1[(2 * p + 1) * 64 + k]);
    }
    if (tid < 32) { sb1[tid] = mb1[tid]; sw2[tid] = mW2[tid]; }
    if (tid == 0) sb2 = mb2[0];
    __syncthreads();

    int n = blockIdx.x * 256 + tid;
    if (n >= N_NODES) return;

    unsigned long long acc[16];
#pragma unroll
    for (int p = 0; p < 16; p++) acc[p] = 0ull;

    const float4* xr = (const float4*)(Hh + (size_t)n * DIM);
#pragma unroll 4
    for (int kk = 0; kk < 16; kk++) {
        float4 x4 = xr[kk];
        float xs[4] = {x4.x, x4.y, x4.z, x4.w};
#pragma unroll
        for (int t = 0; t < 4; t++) {
            int k = kk * 4 + t;
            unsigned long long x2 = dup2(xs[t]);
            const ulonglong2* wrow = (const ulonglong2*)(sWp + k * 16);
#pragma unroll
            for (int q = 0; q < 8; q++) {
                ulonglong2 w2 = wrow[q];
                acc[2 * q]     = ffma2(x2, w2.x, acc[2 * q]);
                acc[2 * q + 1] = ffma2(x2, w2.y, acc[2 * q + 1]);
            }
        }
    }
    float o = sb2;
#pragma unroll
    for (int p = 0; p < 16; p++) {
        o += fmaxf(lo32(acc[p]) + sb1[2 * p], 0.f) * sw2[2 * p];
        o += fmaxf(hi32(acc[p]) + sb1[2 * p + 1], 0.f) * sw2[2 * p + 1];
    }
    out[n] = 1.f / (1.f + __expf(-o));
}

// ---------------- launch ----------------
extern "C" void kernel_launch(void* const* d_in, const int* in_sizes, int n_in,
                              void* d_out, int out_size) {
    const float* x    = (const float*)d_in[0];
    const int*   ei   = (const int*)d_in[1];
    const float* Wl1  = (const float*)d_in[2];
    const float* bl1  = (const float*)d_in[3];
    const float* Wr1  = (const float*)d_in[4];
    const float* g1   = (const float*)d_in[5];
    const float* be1  = (const float*)d_in[6];
    const float* m1   = (const float*)d_in[7];
    const float* v1   = (const float*)d_in[8];
    const float* Wl2  = (const float*)d_in[9];
    const float* bl2  = (const float*)d_in[10];
    const float* Wr2  = (const float*)d_in[11];
    const float* g2   = (const float*)d_in[12];
    const float* be2  = (const float*)d_in[13];
    const float* m2   = (const float*)d_in[14];
    const float* v2   = (const float*)d_in[15];
    const float* mW1  = (const float*)d_in[16];
    const float* mb1  = (const float*)d_in[17];
    const float* mW2  = (const float*)d_in[18];
    const float* mb2  = (const float*)d_in[19];
    float* out = (float*)d_out;

    float* Y; cudaGetSymbolAddress((void**)&Y, g_Y);
    float* Z; cudaGetSymbolAddress((void**)&Z, g_Z);
    float* H; cudaGetSymbolAddress((void**)&H, g_H);

    const int NB_W = (N_NODES * 32 + 255) / 256;   // 12500

    // one-time host-side resources (created outside capture on first call)
    static cudaStream_t sb = nullptr;
    static cudaEvent_t evFork = nullptr, evJoin = nullptr;
    if (!sb) {
        cudaStreamCreateWithFlags(&sb, cudaStreamNonBlocking);
        cudaEventCreateWithFlags(&evFork, cudaEventDisableTiming);
        cudaEventCreateWithFlags(&evJoin, cudaEventDisableTiming);
    }

    // fork: CSR chain on side stream, concurrent with layer-1 GEMM pair
    cudaEventRecord(evFork, 0);
    cudaStreamWaitEvent(sb, evFork, 0);
    k_zero_cnt<<<NB_N, 256, 0, sb>>>();
    k_hist<<<NB_E, 256, 0, sb>>>(ei);
    k_blocksum<<<NB_N, 256, 0, sb>>>();
    k_scatter2<<<NB_N, 256, 0, sb>>>();
    k_fill<<<NB_E, 256, 0, sb>>>(ei);
    cudaEventRecord(evJoin, sb);

    // main stream: layer-1 GEMM pair runs concurrent with CSR build
    k_gemmpair<<<2 * NB_N, 256>>>(x, Wl1, Wr1, Y, Z);
    cudaStreamWaitEvent(0, evJoin, 0);

    // layer 1 aggregate (needs Y, Z, CSR)
    k_agg<<<NB_W, 256>>>(Y, Z, bl1, g1, be1, m1, v1, H);

    // layer 2
    k_gemmpair<<<2 * NB_N, 256>>>(H, Wl2, Wr2, Y, Z);
    k_agg<<<NB_W, 256>>>(Y, Z, bl2, g2, be2, m2, v2, H);

    // head
    k_head<<<NB_N, 256>>>(H, mW1, mb1, mW2, mb2, out);
}

// round 6
// speedup vs baseline: 2.2819x; 1.3551x over previous
#include <cuda_runtime.h>

#define N_NODES 100000
#define E_EDGES 1200000
#define DIM 64
#define EPS_BN 1e-5f
#define NB_N 391      // ceil(N_NODES/256)
#define NB_E 4688     // ceil(E_EDGES/256)
#define NWARPS_G 6250 // N_NODES/16
#define NB_G 782      // ceil(6250/8)

// ---------------- scratch (static device globals; no allocation) ----------------
__device__ int   g_cnt[N_NODES];
__device__ int   g_rowptr[N_NODES + 1];
__device__ int   g_cursor[N_NODES];
__device__ int   g_csr_src[E_EDGES];
__device__ int   g_part[NB_N];
__device__ float g_Y[(size_t)N_NODES * DIM];
__device__ float g_Z[(size_t)N_NODES * DIM];
__device__ float g_H[(size_t)N_NODES * DIM];
// packed B fragments: [pair][ (nt*8+ks)*128 + lane*4 + {hi0,hi1,lo0,lo1} ]
__device__ float g_Bpack[2][16 * 8 * 32 * 4];

// ---------------- tf32 helpers ----------------
__device__ __forceinline__ unsigned cvt_tf32(float x) {
    unsigned r;
    asm("cvt.rna.tf32.f32 %0, %1;" : "=r"(r) : "f"(x));
    return r;
}
__device__ __forceinline__ void mma_tf32(float* c, const unsigned* a, unsigned b0, unsigned b1) {
    asm("mma.sync.aligned.m16n8k8.row.col.f32.tf32.tf32.f32 "
        "{%0,%1,%2,%3}, {%4,%5,%6,%7}, {%8,%9}, {%0,%1,%2,%3};"
        : "+f"(c[0]), "+f"(c[1]), "+f"(c[2]), "+f"(c[3])
        : "r"(a[0]), "r"(a[1]), "r"(a[2]), "r"(a[3]), "r"(b0), "r"(b1));
}

// ---------------- f32x2 helpers (head kernel) ----------------
__device__ __forceinline__ unsigned long long ffma2(unsigned long long a,
                                                    unsigned long long b,
                                                    unsigned long long c) {
    unsigned long long d;
    asm("fma.rn.f32x2 %0, %1, %2, %3;" : "=l"(d) : "l"(a), "l"(b), "l"(c));
    return d;
}
__device__ __forceinline__ unsigned long long dup2(float x) {
    unsigned long long d;
    unsigned u = __float_as_uint(x);
    asm("mov.b64 %0, {%1, %1};" : "=l"(d) : "r"(u));
    return d;
}
__device__ __forceinline__ float lo32(unsigned long long v) {
    return __uint_as_float((unsigned)(v & 0xffffffffull));
}
__device__ __forceinline__ float hi32(unsigned long long v) {
    return __uint_as_float((unsigned)(v >> 32));
}

// ---------------- prepack W fragments (hi/lo tf32), both layers ----------------
// B is col-major K x N with N=128 = [Wl rows | Wr rows]; W[j][k] row-major == B col-major.
__global__ __launch_bounds__(256) void k_prepack(const float* __restrict__ Wl1,
                                                 const float* __restrict__ Wr1,
                                                 const float* __restrict__ Wl2,
                                                 const float* __restrict__ Wr2) {
    int pair = blockIdx.x;
    const float* Wl = pair ? Wl2 : Wl1;
    const float* Wr = pair ? Wr2 : Wr1;
    int t = threadIdx.x;
    for (int idx = t; idx < 4096; idx += 256) {   // 128 tiles * 32 lanes
        int tile = idx >> 5, lane = idx & 31;
        int nt = tile >> 3, ks = tile & 7;
        int n = nt * 8 + (lane >> 2);
        int k = ks * 8 + (lane & 3);
        const float* W = (n < 64) ? Wl : Wr;
        int nn = n & 63;
        float w0 = W[nn * 64 + k];
        float w1 = W[nn * 64 + k + 4];
        unsigned h0 = cvt_tf32(w0), h1 = cvt_tf32(w1);
        unsigned l0 = cvt_tf32(w0 - __uint_as_float(h0));
        unsigned l1 = cvt_tf32(w1 - __uint_as_float(h1));
        float4 v = make_float4(__uint_as_float(h0), __uint_as_float(h1),
                               __uint_as_float(l0), __uint_as_float(l1));
        ((float4*)(g_Bpack[pair]))[idx] = v;
    }
}

// ---------------- tensor-core GEMM pair: [Y|Z] = X @ [Wl|Wr]^T, 3xTF32 ----------------
__global__ __launch_bounds__(256) void k_gemm_tc(const float* __restrict__ X,
                                                 const float* __restrict__ pack,
                                                 float* __restrict__ Y,
                                                 float* __restrict__ Z) {
    int w = (blockIdx.x * 256 + threadIdx.x) >> 5;
    int lane = threadIdx.x & 31;
    if (w >= NWARPS_G) return;

    int g = lane >> 2;          // group id: row within tile
    int tg = lane & 3;          // thread in group
    int r0 = w * 16 + g;        // rows r0, r0+8

    float c[16][4];
#pragma unroll
    for (int nt = 0; nt < 16; nt++) {
        c[nt][0] = 0.f; c[nt][1] = 0.f; c[nt][2] = 0.f; c[nt][3] = 0.f;
    }

    const float4* bp = (const float4*)pack;

#pragma unroll
    for (int ks = 0; ks < 8; ks++) {
        int k = ks * 8 + tg;
        float a00 = X[(size_t)r0 * 64 + k];
        float a10 = X[(size_t)(r0 + 8) * 64 + k];
        float a01 = X[(size_t)r0 * 64 + k + 4];
        float a11 = X[(size_t)(r0 + 8) * 64 + k + 4];

        unsigned ah[4], al[4];
        ah[0] = cvt_tf32(a00); al[0] = cvt_tf32(a00 - __uint_as_float(ah[0]));
        ah[1] = cvt_tf32(a10); al[1] = cvt_tf32(a10 - __uint_as_float(ah[1]));
        ah[2] = cvt_tf32(a01); al[2] = cvt_tf32(a01 - __uint_as_float(ah[2]));
        ah[3] = cvt_tf32(a11); al[3] = cvt_tf32(a11 - __uint_as_float(ah[3]));

#pragma unroll
        for (int nt = 0; nt < 16; nt++) {
            float4 b = bp[(nt * 8 + ks) * 32 + lane];
            unsigned bh0 = __float_as_uint(b.x), bh1 = __float_as_uint(b.y);
            unsigned bl0 = __float_as_uint(b.z), bl1 = __float_as_uint(b.w);
            mma_tf32(c[nt], ah, bh0, bh1);   // hi*hi
            mma_tf32(c[nt], ah, bl0, bl1);   // hi*lo
            mma_tf32(c[nt], al, bh0, bh1);   // lo*hi
        }
    }

    // store: c0,c1 -> row r0 cols 2tg,2tg+1 ; c2,c3 -> row r0+8
#pragma unroll
    for (int nt = 0; nt < 16; nt++) {
        int n0 = nt * 8 + 2 * tg;
        float* O = (nt < 8) ? Y : Z;
        int col = n0 & 63;
        ((float2*)(O + (size_t)r0 * 64 + col))[0] = make_float2(c[nt][0], c[nt][1]);
        ((float2*)(O + (size_t)(r0 + 8) * 64 + col))[0] = make_float2(c[nt][2], c[nt][3]);
    }
}

// ---------------- CSR build ----------------
__global__ void k_zero_cnt() {
    int i = blockIdx.x * blockDim.x + threadIdx.x;
    if (i < N_NODES) g_cnt[i] = 0;
}

__global__ void k_hist(const int* __restrict__ ei) {
    int e = blockIdx.x * blockDim.x + threadIdx.x;
    if (e < E_EDGES) {
        int dst = ei[E_EDGES + e];
        if ((unsigned)dst < N_NODES) atomicAdd(&g_cnt[dst], 1);
    }
}

__global__ __launch_bounds__(256) void k_blocksum() {
    __shared__ int sc[256];
    int t = threadIdx.x;
    int i = blockIdx.x * 256 + t;
    int v = (i < N_NODES) ? g_cnt[i] : 0;
    sc[t] = v;
    __syncthreads();
    for (int off = 128; off > 0; off >>= 1) {
        if (t < off) sc[t] += sc[t + off];
        __syncthreads();
    }
    if (t == 0) g_part[blockIdx.x] = sc[0];
}

__global__ __launch_bounds__(256) void k_scatter2() {
    __shared__ int sc[256];
    __shared__ int sbase[8];
    int t = threadIdx.x;
    int b = blockIdx.x;

    int acc = 0;
    for (int i = t; i < b; i += 256) acc += g_part[i];
#pragma unroll
    for (int o = 16; o > 0; o >>= 1) acc += __shfl_down_sync(0xffffffffu, acc, o);
    if ((t & 31) == 0) sbase[t >> 5] = acc;

    int i = b * 256 + t;
    int v = (i < N_NODES) ? g_cnt[i] : 0;
    sc[t] = v;
    __syncthreads();

    int base = 0;
#pragma unroll
    for (int w = 0; w < 8; w++) base += sbase[w];

    for (int off = 1; off < 256; off <<= 1) {
        int u = (t >= off) ? sc[t - off] : 0;
        __syncthreads();
        sc[t] += u;
        __syncthreads();
    }
    if (i < N_NODES) {
        int pos = base + sc[t] - v;
        g_rowptr[i] = pos;
        g_cursor[i] = pos;
    }
    if (b == NB_N - 1 && t == 255) g_rowptr[N_NODES] = base + sc[255];
}

__global__ void k_fill(const int* __restrict__ ei) {
    int e = blockIdx.x * blockDim.x + threadIdx.x;
    if (e < E_EDGES) {
        int src = ei[e];
        int dst = ei[E_EDGES + e];
        if ((unsigned)dst < N_NODES && (unsigned)src < N_NODES) {
            int pos = atomicAdd(&g_cursor[dst], 1);
            g_csr_src[pos] = src;
        }
    }
}

// ---------------- warp-per-node: H = relu(BN(sum(Y[src])/max(deg,1) + bl + Z)) ----------------
__global__ __launch_bounds__(256) void k_agg(const float* __restrict__ Y,
                                             const float* __restrict__ Z,
                                             const float* __restrict__ bl,
                                             const float* __restrict__ gam,
                                             const float* __restrict__ bet,
                                             const float* __restrict__ mu,
                                             const float* __restrict__ var,
                                             float* __restrict__ H) {
    int warp = (blockIdx.x * blockDim.x + threadIdx.x) >> 5;
    int lane = threadIdx.x & 31;
    if (warp >= N_NODES) return;

    int r0 = g_rowptr[warp];
    int r1 = g_rowptr[warp + 1];

    const float2* Y2 = (const float2*)Y;
    float ax = 0.f, ay = 0.f;

    int e = r0;
    for (; e + 4 <= r1; e += 4) {
        int s0 = g_csr_src[e];
        int s1 = g_csr_src[e + 1];
        int s2 = g_csr_src[e + 2];
        int s3 = g_csr_src[e + 3];
        float2 v0 = Y2[(size_t)s0 * 32 + lane];
        float2 v1 = Y2[(size_t)s1 * 32 + lane];
        float2 v2 = Y2[(size_t)s2 * 32 + lane];
        float2 v3 = Y2[(size_t)s3 * 32 + lane];
        ax += (v0.x + v1.x) + (v2.x + v3.x);
        ay += (v0.y + v1.y) + (v2.y + v3.y);
    }
    if (e + 2 <= r1) {
        int s0 = g_csr_src[e];
        int s1 = g_csr_src[e + 1];
        float2 v0 = Y2[(size_t)s0 * 32 + lane];
        float2 v1 = Y2[(size_t)s1 * 32 + lane];
        ax += v0.x + v1.x;
        ay += v0.y + v1.y;
        e += 2;
    }
    if (e < r1) {
        float2 v = Y2[(size_t)g_csr_src[e] * 32 + lane];
        ax += v.x;
        ay += v.y;
    }

    int deg = r1 - r0;
    float inv = 1.f / (float)(deg > 0 ? deg : 1);

    int j0 = 2 * lane, j1 = 2 * lane + 1;
    float2 z = ((const float2*)Z)[(size_t)warp * 32 + lane];
    float h0 = ax * inv + bl[j0] + z.x;
    float h1 = ay * inv + bl[j1] + z.y;
    float s0 = gam[j0] * rsqrtf(var[j0] + EPS_BN);
    float s1 = gam[j1] * rsqrtf(var[j1] + EPS_BN);
    h0 = fmaxf((h0 - mu[j0]) * s0 + bet[j0], 0.f);
    h1 = fmaxf((h1 - mu[j1]) * s1 + bet[j1], 0.f);
    ((float2*)H)[(size_t)warp * 32 + lane] = make_float2(h0, h1);
}

// ---------------- MLP head ----------------
__global__ __launch_bounds__(256) void k_head(const float* __restrict__ Hh,
                                              const float* __restrict__ mW1,
                                              const float* __restrict__ mb1,
                                              const float* __restrict__ mW2,
                                              const float* __restrict__ mb2,
                                              float* __restrict__ out) {
    __shared__ float2 sWp[64 * 16];
    __shared__ float sb1[32];
    __shared__ float sw2[32];
    __shared__ float sb2;
    int tid = threadIdx.x;
    for (int i = tid; i < 1024; i += 256) {
        int p = i >> 6, k = i & 63;
        sWp[k * 16 + p] = make_float2(mW1[(2 * p) * 64 + k], mW1[(2 * p + 1) * 64 + k]);
    }
    if (tid < 32) { sb1[tid] = mb1[tid]; sw2[tid] = mW2[tid]; }
    if (tid == 0) sb2 = mb2[0];
    __syncthreads();

    int n = blockIdx.x * 256 + tid;
    if (n >= N_NODES) return;

    unsigned long long acc[16];
#pragma unroll
    for (int p = 0; p < 16; p++) acc[p] = 0ull;

    const float4* xr = (const float4*)(Hh + (size_t)n * DIM);
#pragma unroll 4
    for (int kk = 0; kk < 16; kk++) {
        float4 x4 = xr[kk];
        float xs[4] = {x4.x, x4.y, x4.z, x4.w};
#pragma unroll
        for (int t = 0; t < 4; t++) {
            int k = kk * 4 + t;
            unsigned long long x2 = dup2(xs[t]);
            const ulonglong2* wrow = (const ulonglong2*)(sWp + k * 16);
#pragma unroll
            for (int q = 0; q < 8; q++) {
                ulonglong2 w2 = wrow[q];
                acc[2 * q]     = ffma2(x2, w2.x, acc[2 * q]);
                acc[2 * q + 1] = ffma2(x2, w2.y, acc[2 * q + 1]);
            }
        }
    }
    float o = sb2;
#pragma unroll
    for (int p = 0; p < 16; p++) {
        o += fmaxf(lo32(acc[p]) + sb1[2 * p], 0.f) * sw2[2 * p];
        o += fmaxf(hi32(acc[p]) + sb1[2 * p + 1], 0.f) * sw2[2 * p + 1];
    }
    out[n] = 1.f / (1.f + __expf(-o));
}

// ---------------- launch ----------------
extern "C" void kernel_launch(void* const* d_in, const int* in_sizes, int n_in,
                              void* d_out, int out_size) {
    const float* x    = (const float*)d_in[0];
    const int*   ei   = (const int*)d_in[1];
    const float* Wl1  = (const float*)d_in[2];
    const float* bl1  = (const float*)d_in[3];
    const float* Wr1  = (const float*)d_in[4];
    const float* g1   = (const float*)d_in[5];
    const float* be1  = (const float*)d_in[6];
    const float* m1   = (const float*)d_in[7];
    const float* v1   = (const float*)d_in[8];
    const float* Wl2  = (const float*)d_in[9];
    const float* bl2  = (const float*)d_in[10];
    const float* Wr2  = (const float*)d_in[11];
    const float* g2   = (const float*)d_in[12];
    const float* be2  = (const float*)d_in[13];
    const float* m2   = (const float*)d_in[14];
    const float* v2   = (const float*)d_in[15];
    const float* mW1  = (const float*)d_in[16];
    const float* mb1  = (const float*)d_in[17];
    const float* mW2  = (const float*)d_in[18];
    const float* mb2  = (const float*)d_in[19];
    float* out = (float*)d_out;

    float* Y; cudaGetSymbolAddress((void**)&Y, g_Y);
    float* Z; cudaGetSymbolAddress((void**)&Z, g_Z);
    float* H; cudaGetSymbolAddress((void**)&H, g_H);
    float* Bp; cudaGetSymbolAddress((void**)&Bp, g_Bpack);

    const int NB_W = (N_NODES * 32 + 255) / 256;   // 12500

    static cudaStream_t sb = nullptr;
    static cudaEvent_t evFork = nullptr, evJoin = nullptr;
    if (!sb) {
        cudaStreamCreateWithFlags(&sb, cudaStreamNonBlocking);
        cudaEventCreateWithFlags(&evFork, cudaEventDisableTiming);
        cudaEventCreateWithFlags(&evJoin, cudaEventDisableTiming);
    }

    // fork: CSR chain on side stream, concurrent with prepack + layer-1 GEMM
    cudaEventRecord(evFork, 0);
    cudaStreamWaitEvent(sb, evFork, 0);
    k_zero_cnt<<<NB_N, 256, 0, sb>>>();
    k_hist<<<NB_E, 256, 0, sb>>>(ei);
    k_blocksum<<<NB_N, 256, 0, sb>>>();
    k_scatter2<<<NB_N, 256, 0, sb>>>();
    k_fill<<<NB_E, 256, 0, sb>>>(ei);
    cudaEventRecord(evJoin, sb);

    // main stream
    k_prepack<<<2, 256>>>(Wl1, Wr1, Wl2, Wr2);
    k_gemm_tc<<<NB_G, 256>>>(x, Bp, Y, Z);               // layer-1 pair
    cudaStreamWaitEvent(0, evJoin, 0);

    k_agg<<<NB_W, 256>>>(Y, Z, bl1, g1, be1, m1, v1, H);

    k_gemm_tc<<<NB_G, 256>>>(H, Bp + 16384, Y, Z);       // layer-2 pair
    k_agg<<<NB_W, 256>>>(Y, Z, bl2, g2, be2, m2, v2, H);

    k_head<<<NB_N, 256>>>(H, mW1, mb1, mW2, mb2, out);
}